// round 8
// baseline (speedup 1.0000x reference)
#include <cuda_runtime.h>
#include <cuda_fp16.h>
#include <cstdint>
#include <cmath>

#define BB 8
#define LL 2048
#define VV 10000
#define EE 512
#define HH 512
#define NPAD 10112   // 79 * 128
#define TPAD 10112

// ---------------- device-global scratch ----------------
__device__ float g_table[TPAD * HH];          // emb @ W_ih^T + b_ih (padded rows)
__device__ float g_xproj[BB * LL * HH];
__device__ float g_z[BB * LL * HH];
__device__ float g_rowsum[BB * LL];

__device__ __half g_zh[(size_t)BB * LL * HH];        // z fp16 row-major (scores)
__device__ __half g_zTh[(size_t)BB * HH * LL];       // z fp16 transposed (attgemm B)
__device__ __half g_Ph[(size_t)BB * LL * LL];        // exp(scores) fp16; upper-tri stays 0 (BSS)

__device__ __half g_embA[(size_t)TPAD * 1536];       // [emb_hi|emb_lo|emb_hi]
__device__ __half g_WihB[(size_t)HH * 1536];         // [Wih_hi|Wih_hi|Wih_lo]
__device__ __half g_catA[(size_t)BB * LL * 3072];    // [attv_hi|z_hi|attv_lo|z_lo|attv_hi|z_hi]
__device__ __half g_Wc2[(size_t)HH * 3072];          // [Wc_hi|Wc_hi|Wc_lo]
__device__ __half g_decA[(size_t)BB * LL * 1024];    // [dec_hi|dec_lo]  (W_c epilogue)
__device__ __half g_Wd2[(size_t)NPAD * 1024];        // [Wd_hi|Wd_hi]

// ====================== PTX helpers ======================
__device__ __forceinline__ uint32_t smem_u32(const void* p) {
    uint32_t a;
    asm("{ .reg .u64 t; cvta.to.shared.u64 t, %1; cvt.u32.u64 %0, t; }" : "=r"(a) : "l"(p));
    return a;
}
__device__ __forceinline__ void cpa16(uint32_t dst, const void* src) {
    asm volatile("cp.async.cg.shared.global [%0], [%1], 16;" :: "r"(dst), "l"(src) : "memory");
}
__device__ __forceinline__ void ldm_x4(uint32_t* r, uint32_t a) {
    asm volatile("ldmatrix.sync.aligned.m8n8.x4.shared.b16 {%0,%1,%2,%3}, [%4];"
        : "=r"(r[0]), "=r"(r[1]), "=r"(r[2]), "=r"(r[3]) : "r"(a));
}
__device__ __forceinline__ void mma16816(float* d, const uint32_t* a, const uint32_t* b) {
    asm volatile("mma.sync.aligned.m16n8k16.row.col.f32.f16.f16.f32 "
        "{%0,%1,%2,%3}, {%4,%5,%6,%7}, {%8,%9}, {%0,%1,%2,%3};"
        : "+f"(d[0]), "+f"(d[1]), "+f"(d[2]), "+f"(d[3])
        : "r"(a[0]), "r"(a[1]), "r"(a[2]), "r"(a[3]), "r"(b[0]), "r"(b[1]));
}
// packed fp32x2 FMA (Blackwell base ISA)
__device__ __forceinline__ void fma2(unsigned long long& d,
                                     unsigned long long a, unsigned long long b) {
    asm("fma.rn.f32x2 %0, %1, %2, %0;" : "+l"(d) : "l"(a), "l"(b));
}
__device__ __forceinline__ float2 upk2(unsigned long long v) {
    float x, y;
    asm("mov.b64 {%0,%1}, %2;" : "=f"(x), "=f"(y) : "l"(v));
    return make_float2(x, y);
}

// ====================== shared HMMA mainloop ======================
// C_tile[128,128] += A[128 rows, K] * B[128 rows, K]^T ; BK=32, 3-stage cp.async
#define HM_STAGE 20480
#define HM_SMEM (3 * HM_STAGE)

__device__ __forceinline__ void hmma_mainloop(
    const __half* __restrict__ Ab, int lda,
    const __half* __restrict__ Bb, int ldb, int NC,
    uint32_t smb, int tid, int lane, int wm, int wn, float acc[2][8][4])
{
    auto load_stage = [&](int c) {
        const uint32_t sa = smb + (c % 3) * HM_STAGE;
        const uint32_t sbp = sa + 10240;
        const __half* Ag = Ab + c * 32;
        const __half* Bg = Bb + c * 32;
#pragma unroll
        for (int i = 0; i < 2; i++) {
            int ch = tid + i * 256;
            int r = ch >> 2, seg = ch & 3;
            cpa16(sa + r * 80 + seg * 16, Ag + (size_t)r * lda + seg * 8);
        }
#pragma unroll
        for (int i = 0; i < 2; i++) {
            int ch = tid + i * 256;
            int r = ch >> 2, seg = ch & 3;
            cpa16(sbp + r * 80 + seg * 16, Bg + (size_t)r * ldb + seg * 8);
        }
        asm volatile("cp.async.commit_group;" ::: "memory");
    };

    load_stage(0);
    load_stage(1);

    for (int i = 0; i < NC; i++) {
        if (i + 1 < NC) asm volatile("cp.async.wait_group 1;" ::: "memory");
        else            asm volatile("cp.async.wait_group 0;" ::: "memory");
        __syncthreads();
        if (i + 2 < NC) load_stage(i + 2);

        const uint32_t sa = smb + (i % 3) * HM_STAGE;
        const uint32_t sbp = sa + 10240;
#pragma unroll
        for (int ks = 0; ks < 2; ks++) {
            uint32_t areg[2][4];
            uint32_t breg[8][2];
#pragma unroll
            for (int mi = 0; mi < 2; mi++) {
                int row = wm + mi * 16 + (lane & 15);
                ldm_x4(areg[mi], sa + row * 80 + ks * 32 + ((lane >> 4) << 4));
            }
#pragma unroll
            for (int nq = 0; nq < 4; nq++) {
                int n = wn + nq * 16 + (lane & 7) + ((lane >> 4) << 3);
                uint32_t t[4];
                ldm_x4(t, sbp + n * 80 + ks * 32 + (((lane >> 3) & 1) << 4));
                breg[nq * 2][0] = t[0]; breg[nq * 2][1] = t[1];
                breg[nq * 2 + 1][0] = t[2]; breg[nq * 2 + 1][1] = t[3];
            }
#pragma unroll
            for (int mi = 0; mi < 2; mi++)
#pragma unroll
                for (int ni = 0; ni < 8; ni++)
                    mma16816(acc[mi][ni], areg[mi], breg[ni]);
        }
    }
}

// MODE 0: bias -> fp32 C (W_d logits, table)
// MODE 1: bias -> decA hi/lo fp16 (W_c)
// MODE 2: scores: z_h @ z_h^T, exp+mask -> P fp16 (triangular tiles)
// MODE 3: attgemm: P_h @ zT_h^T, scale by 1/rowsum -> catA hi/lo/hi fp16
template<int MODE>
__global__ void __launch_bounds__(256, 2) hmma_kernel(
    const __half* __restrict__ Abase, int lda,
    const __half* __restrict__ Bbase, int ldb,
    const float* __restrict__ aux, void* __restrict__ Cptr,
    int NCin, int Nout, int Nvalid)
{
    extern __shared__ char smem[];
    const uint32_t smb = smem_u32(smem);
    const int tid = threadIdx.x;
    const int wid = tid >> 5, lane = tid & 31;
    const int wm = (wid & 3) * 32, wn = (wid >> 2) * 64;
    const int bm = blockIdx.y * 128, bn = blockIdx.x * 128;
    const int bz = blockIdx.z;

    if (MODE == 2 && blockIdx.x > blockIdx.y) return;

    const __half* Ab;
    const __half* Bb;
    int NC = NCin;
    if (MODE == 2) {
        Ab = Abase + (size_t)bz * LL * HH + (size_t)bm * lda;
        Bb = Abase + (size_t)bz * LL * HH + (size_t)bn * ldb;
    } else if (MODE == 3) {
        Ab = Abase + (size_t)bz * LL * LL + (size_t)bm * lda;
        Bb = Bbase + (size_t)bz * HH * LL + (size_t)bn * ldb;
        NC = (blockIdx.y + 1) * 4;
    } else {
        Ab = Abase + (size_t)bm * lda;
        Bb = Bbase + (size_t)bn * ldb;
    }

    float acc[2][8][4];
#pragma unroll
    for (int mi = 0; mi < 2; mi++)
#pragma unroll
        for (int ni = 0; ni < 8; ni++)
#pragma unroll
            for (int j = 0; j < 4; j++) acc[mi][ni][j] = 0.f;

    hmma_mainloop(Ab, lda, Bb, ldb, NC, smb, tid, lane, wm, wn, acc);

    const int r0 = lane >> 2, c0 = (lane & 3) * 2;

    if (MODE == 0) {
        float* C = (float*)Cptr;
#pragma unroll
        for (int mi = 0; mi < 2; mi++) {
#pragma unroll
            for (int ni = 0; ni < 8; ni++) {
                int gn = bn + wn + ni * 8 + c0;
                if (gn >= Nvalid) continue;
                float b0 = aux[gn], b1 = aux[gn + 1];
                int gm = bm + wm + mi * 16 + r0;
                *reinterpret_cast<float2*>(C + (size_t)gm * Nout + gn) =
                    make_float2(acc[mi][ni][0] + b0, acc[mi][ni][1] + b1);
                *reinterpret_cast<float2*>(C + (size_t)(gm + 8) * Nout + gn) =
                    make_float2(acc[mi][ni][2] + b0, acc[mi][ni][3] + b1);
            }
        }
    } else if (MODE == 1) {
        __half* D = (__half*)Cptr;   // decA [M, 1024]: hi at col, lo at 512+col
#pragma unroll
        for (int mi = 0; mi < 2; mi++) {
#pragma unroll
            for (int ni = 0; ni < 8; ni++) {
                int gn = bn + wn + ni * 8 + c0;
                float b0 = aux[gn], b1 = aux[gn + 1];
#pragma unroll
                for (int half_ : {0, 1}) {
                    int gm = bm + wm + mi * 16 + r0 + half_ * 8;
                    float v0 = acc[mi][ni][half_ * 2 + 0] + b0;
                    float v1 = acc[mi][ni][half_ * 2 + 1] + b1;
                    __half2 hi, lo;
                    hi.x = __float2half_rn(v0);
                    hi.y = __float2half_rn(v1);
                    lo.x = __float2half_rn(v0 - __half2float(hi.x));
                    lo.y = __float2half_rn(v1 - __half2float(hi.y));
                    *reinterpret_cast<__half2*>(D + (size_t)gm * 1024 + gn) = hi;
                    *reinterpret_cast<__half2*>(D + (size_t)gm * 1024 + 512 + gn) = lo;
                }
            }
        }
    } else if (MODE == 2) {
        __half* P = (__half*)Cptr + (size_t)bz * LL * LL;
#pragma unroll
        for (int mi = 0; mi < 2; mi++) {
#pragma unroll
            for (int ni = 0; ni < 8; ni++) {
                int gmc = bn + wn + ni * 8 + c0;       // column m
#pragma unroll
                for (int half_ : {0, 1}) {
                    int gl = bm + wm + mi * 16 + r0 + half_ * 8;
                    float v0 = acc[mi][ni][half_ * 2 + 0];
                    float v1 = acc[mi][ni][half_ * 2 + 1];
                    __half2 e;
                    e.x = __float2half_rn((gmc     < gl) ? __expf(v0) : 0.f);
                    e.y = __float2half_rn((gmc + 1 < gl) ? __expf(v1) : 0.f);
                    *reinterpret_cast<__half2*>(P + (size_t)gl * LL + gmc) = e;
                }
            }
        }
    } else {  // MODE 3: write attv hi/lo/hi directly into catA [row, 3072]
        __half* D = (__half*)Cptr;
        const float* rsb = aux + (size_t)bz * LL;
#pragma unroll
        for (int mi = 0; mi < 2; mi++) {
#pragma unroll
            for (int ni = 0; ni < 8; ni++) {
                int gn = bn + wn + ni * 8 + c0;
#pragma unroll
                for (int half_ : {0, 1}) {
                    int gm = bm + wm + mi * 16 + r0 + half_ * 8;
                    float inv = 1.f / rsb[gm];   // row 0 -> NaN, overwritten by row0_kernel
                    float v0 = acc[mi][ni][half_ * 2 + 0] * inv;
                    float v1 = acc[mi][ni][half_ * 2 + 1] * inv;
                    __half2 hi, lo;
                    hi.x = __float2half_rn(v0);
                    hi.y = __float2half_rn(v1);
                    lo.x = __float2half_rn(v0 - __half2float(hi.x));
                    lo.y = __float2half_rn(v1 - __half2float(hi.y));
                    size_t rb = ((size_t)bz * LL + gm) * 3072;
                    *reinterpret_cast<__half2*>(D + rb + gn) = hi;
                    *reinterpret_cast<__half2*>(D + rb + 1024 + gn) = lo;
                    *reinterpret_cast<__half2*>(D + rb + 2048 + gn) = hi;
                }
            }
        }
    }
}

// ---------------- z prep: zh fp16 + zT fp16 + catA z hi/lo parts ----------------
__global__ void __launch_bounds__(1024) zprep_kernel(
    const float* __restrict__ z, __half* __restrict__ zh, __half* __restrict__ zT,
    __half* __restrict__ catA)
{
    __shared__ __half tile[32][33];
    const int b = blockIdx.z;
    const int t0 = blockIdx.x * 32, j0 = blockIdx.y * 32;
    const int tx = threadIdx.x, ty = threadIdx.y;
    const float* zb = z + (size_t)b * LL * HH;
    float zv = zb[(size_t)(t0 + ty) * HH + j0 + tx];
    __half h = __float2half_rn(zv);
    __half lo = __float2half_rn(zv - __half2float(h));
    zh[(size_t)b * LL * HH + (size_t)(t0 + ty) * HH + j0 + tx] = h;
    size_t rb = ((size_t)b * LL + t0 + ty) * 3072 + j0 + tx;
    catA[rb + 512]  = h;
    catA[rb + 1536] = lo;
    catA[rb + 2560] = h;
    tile[ty][tx] = h;
    __syncthreads();
    zT[(size_t)b * HH * LL + (size_t)(j0 + ty) * LL + t0 + tx] = tile[tx][ty];
}

// ---------------- split fp32 -> fp16 hi/lo (K-concat) ----------------
__global__ void __launch_bounds__(256) split3h_kernel(
    const float* __restrict__ src, int Ksrc,
    __half* __restrict__ dst, int Kdst,
    int off_hi1, int off_hi2, int off_lo, int Mvalid)
{
    int row = blockIdx.y;
    int col = (blockIdx.x * 256 + threadIdx.x) * 2;
    if (col >= Ksrc) return;
    float2 v = make_float2(0.f, 0.f);
    if (row < Mvalid) v = *reinterpret_cast<const float2*>(src + (size_t)row * Ksrc + col);
    __half2 hi, lo;
    hi.x = __float2half_rn(v.x);
    hi.y = __float2half_rn(v.y);
    lo.x = __float2half_rn(v.x - __half2float(hi.x));
    lo.y = __float2half_rn(v.y - __half2float(hi.y));
    size_t rb = (size_t)row * Kdst;
    *reinterpret_cast<__half2*>(dst + rb + off_hi1 + col) = hi;
    *reinterpret_cast<__half2*>(dst + rb + off_hi2 + col) = hi;
    *reinterpret_cast<__half2*>(dst + rb + off_lo + col) = lo;
}

__global__ void __launch_bounds__(256) split2h_kernel(
    const float* __restrict__ src, int Ksrc,
    __half* __restrict__ dst, int Kdst, int off1, int off2, int Mvalid)
{
    int row = blockIdx.y;
    int col = (blockIdx.x * 256 + threadIdx.x) * 2;
    if (col >= Ksrc) return;
    float2 v = make_float2(0.f, 0.f);
    if (row < Mvalid) v = *reinterpret_cast<const float2*>(src + (size_t)row * Ksrc + col);
    __half2 hi;
    hi.x = __float2half_rn(v.x);
    hi.y = __float2half_rn(v.y);
    size_t rb = (size_t)row * Kdst;
    *reinterpret_cast<__half2*>(dst + rb + off1 + col) = hi;
    *reinterpret_cast<__half2*>(dst + rb + off2 + col) = hi;
}

// ---------------- token gather ----------------
__global__ void __launch_bounds__(256) gather_kernel(
    const int* __restrict__ batch, const float* __restrict__ table, float* __restrict__ xproj)
{
    int g = blockIdx.x * 256 + threadIdx.x;
    int row = g >> 7;
    int c = g & 127;
    int tok = batch[row];
    reinterpret_cast<float4*>(xproj)[g] =
        reinterpret_cast<const float4*>(table + (size_t)tok * HH)[c];
}

// ---------------- RNN scan: 8-CTA cluster per batch ----------------
// Per-iter critical path holds only SMEM/DSMEM writes; z goes to GMEM every 8
// steps so the cluster-barrier release drains an STG burst once per 8 iters.
__global__ void __launch_bounds__(512, 1) rnn_kernel(
    const float* __restrict__ xproj, const float* __restrict__ Whh,
    const float* __restrict__ bhh, float* __restrict__ z)
{
    __shared__ __align__(16) float hbuf[2][8 * 80];
    __shared__ float zstage[8][64];
    unsigned rank;
    asm("mov.u32 %0, %%cluster_ctarank;" : "=r"(rank));
    const int batch = blockIdx.x >> 3;
    const int tid = threadIdx.x;
    const int jl = tid >> 3;
    const int ks = tid & 7;
    const int j = (int)rank * 64 + jl;

    unsigned long long w2[32];
    const ulonglong2* wp = reinterpret_cast<const ulonglong2*>(Whh + (size_t)j * HH + ks * 64);
#pragma unroll
    for (int i = 0; i < 16; i++) {
        ulonglong2 v = wp[i];
        w2[2 * i] = v.x; w2[2 * i + 1] = v.y;
    }
    const float bj = bhh[j];

    for (int i = tid; i < 2 * 8 * 80; i += 512) (&hbuf[0][0])[i] = 0.f;

    uint32_t base_u32 = smem_u32(&hbuf[0][0]);
    const int jpad = (j >> 6) * 80 + (j & 63);

    __syncthreads();
    asm volatile("barrier.cluster.arrive.aligned;\n\tbarrier.cluster.wait.aligned;" ::: "memory");

    const float* xp = xproj + (size_t)batch * LL * HH;
    float* zb = z + (size_t)batch * LL * HH;

    // flush indices: each thread stores one of 8x64 staged values
    const int fr = tid >> 6;              // staged step 0..7
    const int fc = tid & 63;              // local column 0..63
    const int fj = (int)rank * 64 + fc;   // global column

    int cur = 0;
    float xnext = xp[j];
    for (int t0 = 0; t0 < LL; t0 += 8) {
#pragma unroll 1
        for (int tt = 0; tt < 8; tt++) {
            const int t = t0 + tt;
            const float xcur = xnext;

            const ulonglong2* hp = reinterpret_cast<const ulonglong2*>(&hbuf[cur][ks * 80]);
            unsigned long long acc[4] = {0ull, 0ull, 0ull, 0ull};
#pragma unroll
            for (int i = 0; i < 16; i++) {
                ulonglong2 hv = hp[i];
                fma2(acc[(i & 1) * 2],     w2[2 * i],     hv.x);
                fma2(acc[(i & 1) * 2 + 1], w2[2 * i + 1], hv.y);
            }
            float2 f0 = upk2(acc[0]), f1 = upk2(acc[1]);
            float2 f2 = upk2(acc[2]), f3 = upk2(acc[3]);
            float s = ((f0.x + f0.y) + (f1.x + f1.y)) + ((f2.x + f2.y) + (f3.x + f3.y));
            s += __shfl_xor_sync(0xffffffffu, s, 1);
            s += __shfl_xor_sync(0xffffffffu, s, 2);
            s += __shfl_xor_sync(0xffffffffu, s, 4);

            const int nxt = cur ^ 1;
            if (ks == 0) {
                float hv = tanhf(s + xcur + bj);
                zstage[tt][jl] = hv;                       // STS, not STG
                uint32_t laddr = base_u32 + (uint32_t)(nxt * 640 + jpad) * 4u;
#pragma unroll
                for (int r = 0; r < 8; r++) {
                    if (r == (int)rank) {
                        hbuf[nxt][jpad] = hv;
                    } else {
                        uint32_t ra;
                        asm volatile("mapa.shared::cluster.u32 %0, %1, %2;" : "=r"(ra) : "r"(laddr), "r"(r));
                        asm volatile("st.shared::cluster.f32 [%0], %1;" :: "r"(ra), "f"(hv) : "memory");
                    }
                }
            }
            asm volatile("barrier.cluster.arrive.aligned;" ::: "memory");
            // hide xnext prefetch behind barrier propagation
            if (t + 1 < LL) xnext = xp[(size_t)(t + 1) * HH + j];
            cur = nxt;
            asm volatile("barrier.cluster.wait.aligned;" ::: "memory");
        }
        // bulk z flush: 512 threads, one value each (visible after the cluster wait)
        zb[(size_t)(t0 + fr) * HH + fj] = zstage[fr][fc];
    }
}

// ---------------- row sums of fp16 P ----------------
__global__ void __launch_bounds__(256) rowsum_h_kernel(
    const __half* __restrict__ P, float* __restrict__ rs)
{
    int warp = threadIdx.x >> 5, lane = threadIdx.x & 31;
    int row = blockIdx.x * 8 + warp;
    const uint4* pr = reinterpret_cast<const uint4*>(P + (size_t)row * LL);
    float s = 0.f;
#pragma unroll
    for (int i = 0; i < 8; i++) {
        uint4 v = pr[i * 32 + lane];
        __half2 h0 = *reinterpret_cast<__half2*>(&v.x);
        __half2 h1 = *reinterpret_cast<__half2*>(&v.y);
        __half2 h2 = *reinterpret_cast<__half2*>(&v.z);
        __half2 h3 = *reinterpret_cast<__half2*>(&v.w);
        float2 f0 = __half22float2(h0), f1 = __half22float2(h1);
        float2 f2 = __half22float2(h2), f3 = __half22float2(h3);
        s += (f0.x + f0.y) + (f1.x + f1.y) + (f2.x + f2.y) + (f3.x + f3.y);
    }
#pragma unroll
    for (int m = 16; m; m >>= 1) s += __shfl_xor_sync(0xffffffffu, s, m);
    if (lane == 0) rs[row] = s;
}

// ---------------- row 0 fixup: mean of z -> catA hi/lo/hi ----------------
__global__ void __launch_bounds__(512) row0_kernel(
    const float* __restrict__ z, __half* __restrict__ catA)
{
    int b = blockIdx.x, h = threadIdx.x;
    const float* zb = z + (size_t)b * LL * HH + h;
    float s = 0.f;
#pragma unroll 8
    for (int m = 0; m < LL; m++) s += zb[(size_t)m * HH];
    float v = s * (1.0f / LL);
    __half hi = __float2half_rn(v);
    __half lo = __float2half_rn(v - __half2float(hi));
    size_t rb = (size_t)b * LL * 3072;
    catA[rb + h] = hi;
    catA[rb + 1024 + h] = lo;
    catA[rb + 2048 + h] = hi;
}

// ---------------- launch ----------------
extern "C" void kernel_launch(void* const* d_in, const int* in_sizes, int n_in,
                              void* d_out, int out_size)
{
    (void)in_sizes; (void)n_in; (void)out_size;
    const int*   batch = (const int*)  d_in[0];
    const float* emb   = (const float*)d_in[1];
    const float* W_ih  = (const float*)d_in[2];
    const float* b_ih  = (const float*)d_in[3];
    const float* W_hh  = (const float*)d_in[4];
    const float* b_hh  = (const float*)d_in[5];
    const float* W_c   = (const float*)d_in[6];
    const float* b_c   = (const float*)d_in[7];
    const float* W_d   = (const float*)d_in[8];
    const float* b_d   = (const float*)d_in[9];
    float* out = (float*)d_out;

    float *table, *xproj, *zbuf, *rs;
    __half *zh, *zTh, *Ph, *embA, *WihB, *catA, *Wc2, *decA, *Wd2;
    cudaGetSymbolAddress((void**)&table, g_table);
    cudaGetSymbolAddress((void**)&xproj, g_xproj);
    cudaGetSymbolAddress((void**)&zbuf,  g_z);
    cudaGetSymbolAddress((void**)&rs,    g_rowsum);
    cudaGetSymbolAddress((void**)&zh,    g_zh);
    cudaGetSymbolAddress((void**)&zTh,   g_zTh);
    cudaGetSymbolAddress((void**)&Ph,    g_Ph);
    cudaGetSymbolAddress((void**)&embA,  g_embA);
    cudaGetSymbolAddress((void**)&WihB,  g_WihB);
    cudaGetSymbolAddress((void**)&catA,  g_catA);
    cudaGetSymbolAddress((void**)&Wc2,   g_Wc2);
    cudaGetSymbolAddress((void**)&decA,  g_decA);
    cudaGetSymbolAddress((void**)&Wd2,   g_Wd2);

    cudaFuncSetAttribute(hmma_kernel<0>, cudaFuncAttributeMaxDynamicSharedMemorySize, HM_SMEM);
    cudaFuncSetAttribute(hmma_kernel<1>, cudaFuncAttributeMaxDynamicSharedMemorySize, HM_SMEM);
    cudaFuncSetAttribute(hmma_kernel<2>, cudaFuncAttributeMaxDynamicSharedMemorySize, HM_SMEM);
    cudaFuncSetAttribute(hmma_kernel<3>, cudaFuncAttributeMaxDynamicSharedMemorySize, HM_SMEM);

    // 1. table = emb @ W_ih^T + b_ih via HMMA 3-term split (K=1536)
    split3h_kernel<<<dim3(1, TPAD), 256>>>(emb, 512, embA, 1536, 0, 1024, 512, VV);
    split3h_kernel<<<dim3(1, HH),   256>>>(W_ih, 512, WihB, 1536, 0, 512, 1024, HH);
    hmma_kernel<0><<<dim3(HH / 128, TPAD / 128), 256, HM_SMEM>>>(
        embA, 1536, WihB, 1536, b_ih, table, 1536 / 32, HH, HH);

    // 2. xproj = table[batch]
    gather_kernel<<<(BB * LL * HH / 4) / 256, 256>>>(batch, table, xproj);

    // 3. RNN scan (8-CTA cluster per batch, staged z flush)
    {
        cudaLaunchConfig_t cfg = {};
        cfg.gridDim = dim3(64, 1, 1);
        cfg.blockDim = dim3(512, 1, 1);
        cfg.dynamicSmemBytes = 0;
        cfg.stream = 0;
        cudaLaunchAttribute attr[1];
        attr[0].id = cudaLaunchAttributeClusterDimension;
        attr[0].val.clusterDim.x = 8;
        attr[0].val.clusterDim.y = 1;
        attr[0].val.clusterDim.z = 1;
        cfg.attrs = attr;
        cfg.numAttrs = 1;
        cudaLaunchKernelEx(&cfg, rnn_kernel, (const float*)xproj, W_hh, b_hh, zbuf);
    }

    // 4. z -> fp16 (row-major + transposed + catA z-parts)
    zprep_kernel<<<dim3(LL / 32, HH / 32, BB), dim3(32, 32)>>>(zbuf, zh, zTh, catA);

    // 5. P = exp(mask(z zT)) fp16 via HMMA (triangular tiles)
    hmma_kernel<2><<<dim3(LL / 128, LL / 128, BB), 256, HM_SMEM>>>(
        zh, HH, zh, HH, nullptr, Ph, HH / 32, LL, LL);

    // 6. row sums
    rowsum_h_kernel<<<(BB * LL) / 8, 256>>>(Ph, rs);

    // 7. attv -> catA hi/lo/hi via HMMA (triangular K)
    hmma_kernel<3><<<dim3(HH / 128, LL / 128, BB), 256, HM_SMEM>>>(
        Ph, LL, zTh, LL, rs, catA, 0, HH, HH);

    // 8. row 0 fixup
    row0_kernel<<<BB, 512>>>(zbuf, catA);

    // 9. dec (fp16 hi/lo, fused) = [attv | z] @ W_c^T + b_c via 3-term split (K=3072)
    split3h_kernel<<<dim3(2, HH), 256>>>(W_c, 1024, Wc2, 3072, 0, 1024, 2048, HH);
    hmma_kernel<1><<<dim3(HH / 128, BB * LL / 128), 256, HM_SMEM>>>(
        catA, 3072, Wc2, 3072, b_c, decA, 3072 / 32, 1024, HH);

    // 10. logits = dec @ W_d^T + b_d via 2-term split (K=1024)
    split2h_kernel<<<dim3(1, NPAD), 256>>>(W_d, 512, Wd2, 1024, 0, 512, VV);
    hmma_kernel<0><<<dim3(NPAD / 128, BB * LL / 128), 256, HM_SMEM>>>(
        decA, 1024, Wd2, 1024, b_d, out, 1024 / 32, VV, VV);
}

// round 9
// speedup vs baseline: 1.8131x; 1.8131x over previous
#include <cuda_runtime.h>
#include <cuda_fp16.h>
#include <cstdint>
#include <cmath>

#define BB 8
#define LL 2048
#define VV 10000
#define EE 512
#define HH 512
#define NPAD 10112   // 79 * 128
#define TPAD 10112

// ---------------- device-global scratch ----------------
__device__ float g_table[TPAD * HH];          // emb @ W_ih^T + b_ih (padded rows)
__device__ float g_xproj[BB * LL * HH];
__device__ float g_z[BB * LL * HH];
__device__ float g_rowsum[BB * LL];

__device__ __half g_zh[(size_t)BB * LL * HH];        // z fp16 row-major (scores)
__device__ __half g_zTh[(size_t)BB * HH * LL];       // z fp16 transposed (attgemm B)
__device__ __half g_Ph[(size_t)BB * LL * LL];        // exp(scores) fp16; upper-tri stays 0 (BSS)

__device__ __half g_embA[(size_t)TPAD * 1536];       // [emb_hi|emb_lo|emb_hi]
__device__ __half g_WihB[(size_t)HH * 1536];         // [Wih_hi|Wih_hi|Wih_lo]
__device__ __half g_catA[(size_t)BB * LL * 3072];    // [attv_hi|z_hi|attv_lo|z_lo|attv_hi|z_hi]
__device__ __half g_Wc2[(size_t)HH * 3072];          // [Wc_hi|Wc_hi|Wc_lo]
__device__ __half g_decA[(size_t)BB * LL * 1024];    // [dec_hi|dec_lo]  (W_c epilogue)
__device__ __half g_Wd2[(size_t)NPAD * 1024];        // [Wd_hi|Wd_hi]

// ====================== PTX helpers ======================
__device__ __forceinline__ uint32_t smem_u32(const void* p) {
    uint32_t a;
    asm("{ .reg .u64 t; cvta.to.shared.u64 t, %1; cvt.u32.u64 %0, t; }" : "=r"(a) : "l"(p));
    return a;
}
__device__ __forceinline__ void cpa16(uint32_t dst, const void* src) {
    asm volatile("cp.async.cg.shared.global [%0], [%1], 16;" :: "r"(dst), "l"(src) : "memory");
}
__device__ __forceinline__ void ldm_x4(uint32_t* r, uint32_t a) {
    asm volatile("ldmatrix.sync.aligned.m8n8.x4.shared.b16 {%0,%1,%2,%3}, [%4];"
        : "=r"(r[0]), "=r"(r[1]), "=r"(r[2]), "=r"(r[3]) : "r"(a));
}
__device__ __forceinline__ void mma16816(float* d, const uint32_t* a, const uint32_t* b) {
    asm volatile("mma.sync.aligned.m16n8k16.row.col.f32.f16.f16.f32 "
        "{%0,%1,%2,%3}, {%4,%5,%6,%7}, {%8,%9}, {%0,%1,%2,%3};"
        : "+f"(d[0]), "+f"(d[1]), "+f"(d[2]), "+f"(d[3])
        : "r"(a[0]), "r"(a[1]), "r"(a[2]), "r"(a[3]), "r"(b[0]), "r"(b[1]));
}
// packed fp32x2 FMA (Blackwell base ISA)
__device__ __forceinline__ void fma2(unsigned long long& d,
                                     unsigned long long a, unsigned long long b) {
    asm("fma.rn.f32x2 %0, %1, %2, %0;" : "+l"(d) : "l"(a), "l"(b));
}
__device__ __forceinline__ float2 upk2(unsigned long long v) {
    float x, y;
    asm("mov.b64 {%0,%1}, %2;" : "=f"(x), "=f"(y) : "l"(v));
    return make_float2(x, y);
}

// ====================== shared HMMA mainloop ======================
// C_tile[128,128] += A[128 rows, K] * B[128 rows, K]^T ; BK=32, 3-stage cp.async
#define HM_STAGE 20480
#define HM_SMEM (3 * HM_STAGE)

__device__ __forceinline__ void hmma_mainloop(
    const __half* __restrict__ Ab, int lda,
    const __half* __restrict__ Bb, int ldb, int NC,
    uint32_t smb, int tid, int lane, int wm, int wn, float acc[2][8][4])
{
    auto load_stage = [&](int c) {
        const uint32_t sa = smb + (c % 3) * HM_STAGE;
        const uint32_t sbp = sa + 10240;
        const __half* Ag = Ab + c * 32;
        const __half* Bg = Bb + c * 32;
#pragma unroll
        for (int i = 0; i < 2; i++) {
            int ch = tid + i * 256;
            int r = ch >> 2, seg = ch & 3;
            cpa16(sa + r * 80 + seg * 16, Ag + (size_t)r * lda + seg * 8);
        }
#pragma unroll
        for (int i = 0; i < 2; i++) {
            int ch = tid + i * 256;
            int r = ch >> 2, seg = ch & 3;
            cpa16(sbp + r * 80 + seg * 16, Bg + (size_t)r * ldb + seg * 8);
        }
        asm volatile("cp.async.commit_group;" ::: "memory");
    };

    load_stage(0);
    load_stage(1);

    for (int i = 0; i < NC; i++) {
        if (i + 1 < NC) asm volatile("cp.async.wait_group 1;" ::: "memory");
        else            asm volatile("cp.async.wait_group 0;" ::: "memory");
        __syncthreads();
        if (i + 2 < NC) load_stage(i + 2);

        const uint32_t sa = smb + (i % 3) * HM_STAGE;
        const uint32_t sbp = sa + 10240;
#pragma unroll
        for (int ks = 0; ks < 2; ks++) {
            uint32_t areg[2][4];
            uint32_t breg[8][2];
#pragma unroll
            for (int mi = 0; mi < 2; mi++) {
                int row = wm + mi * 16 + (lane & 15);
                ldm_x4(areg[mi], sa + row * 80 + ks * 32 + ((lane >> 4) << 4));
            }
#pragma unroll
            for (int nq = 0; nq < 4; nq++) {
                int n = wn + nq * 16 + (lane & 7) + ((lane >> 4) << 3);
                uint32_t t[4];
                ldm_x4(t, sbp + n * 80 + ks * 32 + (((lane >> 3) & 1) << 4));
                breg[nq * 2][0] = t[0]; breg[nq * 2][1] = t[1];
                breg[nq * 2 + 1][0] = t[2]; breg[nq * 2 + 1][1] = t[3];
            }
#pragma unroll
            for (int mi = 0; mi < 2; mi++)
#pragma unroll
                for (int ni = 0; ni < 8; ni++)
                    mma16816(acc[mi][ni], areg[mi], breg[ni]);
        }
    }
}

// MODE 0: bias -> fp32 C (W_d logits, table)
// MODE 1: bias -> decA hi/lo fp16 (W_c)
// MODE 2: scores: z_h @ z_h^T, exp+mask -> P fp16 (triangular tiles)
// MODE 3: attgemm: P_h @ zT_h^T, scale by 1/rowsum -> catA hi/lo/hi fp16
template<int MODE>
__global__ void __launch_bounds__(256, 2) hmma_kernel(
    const __half* __restrict__ Abase, int lda,
    const __half* __restrict__ Bbase, int ldb,
    const float* __restrict__ aux, void* __restrict__ Cptr,
    int NCin, int Nout, int Nvalid)
{
    extern __shared__ char smem[];
    const uint32_t smb = smem_u32(smem);
    const int tid = threadIdx.x;
    const int wid = tid >> 5, lane = tid & 31;
    const int wm = (wid & 3) * 32, wn = (wid >> 2) * 64;
    const int bm = blockIdx.y * 128, bn = blockIdx.x * 128;
    const int bz = blockIdx.z;

    if (MODE == 2 && blockIdx.x > blockIdx.y) return;

    const __half* Ab;
    const __half* Bb;
    int NC = NCin;
    if (MODE == 2) {
        Ab = Abase + (size_t)bz * LL * HH + (size_t)bm * lda;
        Bb = Abase + (size_t)bz * LL * HH + (size_t)bn * ldb;
    } else if (MODE == 3) {
        Ab = Abase + (size_t)bz * LL * LL + (size_t)bm * lda;
        Bb = Bbase + (size_t)bz * HH * LL + (size_t)bn * ldb;
        NC = (blockIdx.y + 1) * 4;
    } else {
        Ab = Abase + (size_t)bm * lda;
        Bb = Bbase + (size_t)bn * ldb;
    }

    float acc[2][8][4];
#pragma unroll
    for (int mi = 0; mi < 2; mi++)
#pragma unroll
        for (int ni = 0; ni < 8; ni++)
#pragma unroll
            for (int j = 0; j < 4; j++) acc[mi][ni][j] = 0.f;

    hmma_mainloop(Ab, lda, Bb, ldb, NC, smb, tid, lane, wm, wn, acc);

    const int r0 = lane >> 2, c0 = (lane & 3) * 2;

    if (MODE == 0) {
        float* C = (float*)Cptr;
#pragma unroll
        for (int mi = 0; mi < 2; mi++) {
#pragma unroll
            for (int ni = 0; ni < 8; ni++) {
                int gn = bn + wn + ni * 8 + c0;
                if (gn >= Nvalid) continue;
                float b0 = aux[gn], b1 = aux[gn + 1];
                int gm = bm + wm + mi * 16 + r0;
                *reinterpret_cast<float2*>(C + (size_t)gm * Nout + gn) =
                    make_float2(acc[mi][ni][0] + b0, acc[mi][ni][1] + b1);
                *reinterpret_cast<float2*>(C + (size_t)(gm + 8) * Nout + gn) =
                    make_float2(acc[mi][ni][2] + b0, acc[mi][ni][3] + b1);
            }
        }
    } else if (MODE == 1) {
        __half* D = (__half*)Cptr;   // decA [M, 1024]: hi at col, lo at 512+col
#pragma unroll
        for (int mi = 0; mi < 2; mi++) {
#pragma unroll
            for (int ni = 0; ni < 8; ni++) {
                int gn = bn + wn + ni * 8 + c0;
                float b0 = aux[gn], b1 = aux[gn + 1];
#pragma unroll
                for (int half_ : {0, 1}) {
                    int gm = bm + wm + mi * 16 + r0 + half_ * 8;
                    float v0 = acc[mi][ni][half_ * 2 + 0] + b0;
                    float v1 = acc[mi][ni][half_ * 2 + 1] + b1;
                    __half2 hi, lo;
                    hi.x = __float2half_rn(v0);
                    hi.y = __float2half_rn(v1);
                    lo.x = __float2half_rn(v0 - __half2float(hi.x));
                    lo.y = __float2half_rn(v1 - __half2float(hi.y));
                    *reinterpret_cast<__half2*>(D + (size_t)gm * 1024 + gn) = hi;
                    *reinterpret_cast<__half2*>(D + (size_t)gm * 1024 + 512 + gn) = lo;
                }
            }
        }
    } else if (MODE == 2) {
        __half* P = (__half*)Cptr + (size_t)bz * LL * LL;
#pragma unroll
        for (int mi = 0; mi < 2; mi++) {
#pragma unroll
            for (int ni = 0; ni < 8; ni++) {
                int gmc = bn + wn + ni * 8 + c0;       // column m
#pragma unroll
                for (int half_ : {0, 1}) {
                    int gl = bm + wm + mi * 16 + r0 + half_ * 8;
                    float v0 = acc[mi][ni][half_ * 2 + 0];
                    float v1 = acc[mi][ni][half_ * 2 + 1];
                    __half2 e;
                    e.x = __float2half_rn((gmc     < gl) ? __expf(v0) : 0.f);
                    e.y = __float2half_rn((gmc + 1 < gl) ? __expf(v1) : 0.f);
                    *reinterpret_cast<__half2*>(P + (size_t)gl * LL + gmc) = e;
                }
            }
        }
    } else {  // MODE 3: write attv hi/lo/hi directly into catA [row, 3072]
        __half* D = (__half*)Cptr;
        const float* rsb = aux + (size_t)bz * LL;
#pragma unroll
        for (int mi = 0; mi < 2; mi++) {
#pragma unroll
            for (int ni = 0; ni < 8; ni++) {
                int gn = bn + wn + ni * 8 + c0;
#pragma unroll
                for (int half_ : {0, 1}) {
                    int gm = bm + wm + mi * 16 + r0 + half_ * 8;
                    float inv = 1.f / rsb[gm];   // row 0 -> NaN, overwritten by row0_kernel
                    float v0 = acc[mi][ni][half_ * 2 + 0] * inv;
                    float v1 = acc[mi][ni][half_ * 2 + 1] * inv;
                    __half2 hi, lo;
                    hi.x = __float2half_rn(v0);
                    hi.y = __float2half_rn(v1);
                    lo.x = __float2half_rn(v0 - __half2float(hi.x));
                    lo.y = __float2half_rn(v1 - __half2float(hi.y));
                    size_t rb = ((size_t)bz * LL + gm) * 3072;
                    *reinterpret_cast<__half2*>(D + rb + gn) = hi;
                    *reinterpret_cast<__half2*>(D + rb + 1024 + gn) = lo;
                    *reinterpret_cast<__half2*>(D + rb + 2048 + gn) = hi;
                }
            }
        }
    }
}

// ---------------- z prep: zh fp16 + zT fp16 + catA z hi/lo parts ----------------
__global__ void __launch_bounds__(1024) zprep_kernel(
    const float* __restrict__ z, __half* __restrict__ zh, __half* __restrict__ zT,
    __half* __restrict__ catA)
{
    __shared__ __half tile[32][33];
    const int b = blockIdx.z;
    const int t0 = blockIdx.x * 32, j0 = blockIdx.y * 32;
    const int tx = threadIdx.x, ty = threadIdx.y;
    const float* zb = z + (size_t)b * LL * HH;
    float zv = zb[(size_t)(t0 + ty) * HH + j0 + tx];
    __half h = __float2half_rn(zv);
    __half lo = __float2half_rn(zv - __half2float(h));
    zh[(size_t)b * LL * HH + (size_t)(t0 + ty) * HH + j0 + tx] = h;
    size_t rb = ((size_t)b * LL + t0 + ty) * 3072 + j0 + tx;
    catA[rb + 512]  = h;
    catA[rb + 1536] = lo;
    catA[rb + 2560] = h;
    tile[ty][tx] = h;
    __syncthreads();
    zT[(size_t)b * HH * LL + (size_t)(j0 + ty) * LL + t0 + tx] = tile[tx][ty];
}

// ---------------- split fp32 -> fp16 hi/lo (K-concat) ----------------
__global__ void __launch_bounds__(256) split3h_kernel(
    const float* __restrict__ src, int Ksrc,
    __half* __restrict__ dst, int Kdst,
    int off_hi1, int off_hi2, int off_lo, int Mvalid)
{
    int row = blockIdx.y;
    int col = (blockIdx.x * 256 + threadIdx.x) * 2;
    if (col >= Ksrc) return;
    float2 v = make_float2(0.f, 0.f);
    if (row < Mvalid) v = *reinterpret_cast<const float2*>(src + (size_t)row * Ksrc + col);
    __half2 hi, lo;
    hi.x = __float2half_rn(v.x);
    hi.y = __float2half_rn(v.y);
    lo.x = __float2half_rn(v.x - __half2float(hi.x));
    lo.y = __float2half_rn(v.y - __half2float(hi.y));
    size_t rb = (size_t)row * Kdst;
    *reinterpret_cast<__half2*>(dst + rb + off_hi1 + col) = hi;
    *reinterpret_cast<__half2*>(dst + rb + off_hi2 + col) = hi;
    *reinterpret_cast<__half2*>(dst + rb + off_lo + col) = lo;
}

__global__ void __launch_bounds__(256) split2h_kernel(
    const float* __restrict__ src, int Ksrc,
    __half* __restrict__ dst, int Kdst, int off1, int off2, int Mvalid)
{
    int row = blockIdx.y;
    int col = (blockIdx.x * 256 + threadIdx.x) * 2;
    if (col >= Ksrc) return;
    float2 v = make_float2(0.f, 0.f);
    if (row < Mvalid) v = *reinterpret_cast<const float2*>(src + (size_t)row * Ksrc + col);
    __half2 hi;
    hi.x = __float2half_rn(v.x);
    hi.y = __float2half_rn(v.y);
    size_t rb = (size_t)row * Kdst;
    *reinterpret_cast<__half2*>(dst + rb + off1 + col) = hi;
    *reinterpret_cast<__half2*>(dst + rb + off2 + col) = hi;
}

// ---------------- token gather ----------------
__global__ void __launch_bounds__(256) gather_kernel(
    const int* __restrict__ batch, const float* __restrict__ table, float* __restrict__ xproj)
{
    int g = blockIdx.x * 256 + threadIdx.x;
    int row = g >> 7;
    int c = g & 127;
    int tok = batch[row];
    reinterpret_cast<float4*>(xproj)[g] =
        reinterpret_cast<const float4*>(table + (size_t)tok * HH)[c];
}

// ---------------- RNN scan v3: 8-CTA cluster, 256 thr, conflict-free k-interleave ----------------
// Thread (jl, ks): output j = rank*64+jl, k-slice ks in 0..3.
// Thread's k-elements are float4 slots {4i+ks : i=0..31} of h (order-invariant dot).
// h stored contiguous (512 floats) -> warp LDS.128 reads 4 consecutive float4s,
// 8-way broadcast, conflict-free. Exchange: writers commit 64 local values,
// __syncthreads, then 112 threads push 16 float4 x 7 peers via st.shared::cluster.
__global__ void __launch_bounds__(256, 1) rnn_kernel(
    const float* __restrict__ xproj, const float* __restrict__ Whh,
    const float* __restrict__ bhh, float* __restrict__ z)
{
    __shared__ __align__(16) float hbuf[2][512];
    __shared__ float zstage[8][64];
    unsigned rank;
    asm("mov.u32 %0, %%cluster_ctarank;" : "=r"(rank));
    const int batch = blockIdx.x >> 3;
    const int tid = threadIdx.x;
    const int jl = tid >> 2;        // output 0..63
    const int ks = tid & 3;         // k-slice 0..3
    const int j = (int)rank * 64 + jl;

    // W row j, interleaved: w float4 slot i comes from global float4 index 4*i+ks
    unsigned long long w2[64];
    {
        const ulonglong2* wr = reinterpret_cast<const ulonglong2*>(Whh + (size_t)j * HH);
#pragma unroll
        for (int i = 0; i < 32; i++) {
            ulonglong2 q = wr[i * 4 + ks];
            w2[2 * i] = q.x; w2[2 * i + 1] = q.y;
        }
    }
    const float bj = bhh[j];

    for (int i = tid; i < 2 * 512; i += 256) (&hbuf[0][0])[i] = 0.f;

    uint32_t base_u32 = smem_u32(&hbuf[0][0]);

    __syncthreads();
    asm volatile("barrier.cluster.arrive.aligned;\n\tbarrier.cluster.wait.aligned;" ::: "memory");

    const float* xp = xproj + (size_t)batch * LL * HH;
    float* zb = z + (size_t)batch * LL * HH;

    // pusher mapping: tid<112 -> peer p = tid>>4 (skip own rank), float4 slot tid&15
    const int pr_raw = tid >> 4;                     // 0..6 for tid<112
    const int pr = (pr_raw >= (int)rank) ? pr_raw + 1 : pr_raw;
    const int pslot = tid & 15;

    int cur = 0;
    float xnext = (ks == 0) ? xp[j] : 0.f;
    for (int t0 = 0; t0 < LL; t0 += 8) {
#pragma unroll 1
        for (int tt = 0; tt < 8; tt++) {
            const int t = t0 + tt;
            const float xcur = xnext;

            const ulonglong2* hp = reinterpret_cast<const ulonglong2*>(&hbuf[cur][0]);
            unsigned long long acc0 = 0ull, acc1 = 0ull, acc2 = 0ull, acc3 = 0ull;
#pragma unroll
            for (int i = 0; i < 16; i++) {
                ulonglong2 hv0 = hp[(2 * i) * 4 + ks];
                ulonglong2 hv1 = hp[(2 * i + 1) * 4 + ks];
                fma2(acc0, w2[4 * i + 0], hv0.x);
                fma2(acc1, w2[4 * i + 1], hv0.y);
                fma2(acc2, w2[4 * i + 2], hv1.x);
                fma2(acc3, w2[4 * i + 3], hv1.y);
            }
            float2 f0 = upk2(acc0), f1 = upk2(acc1);
            float2 f2 = upk2(acc2), f3 = upk2(acc3);
            float s = ((f0.x + f0.y) + (f1.x + f1.y)) + ((f2.x + f2.y) + (f3.x + f3.y));
            s += __shfl_xor_sync(0xffffffffu, s, 1);
            s += __shfl_xor_sync(0xffffffffu, s, 2);

            const int nxt = cur ^ 1;
            if (ks == 0) {
                float hv = tanhf(s + xcur + bj);
                zstage[tt][jl] = hv;
                hbuf[nxt][j] = hv;          // own slice, local copy
            }
            __syncthreads();                 // local slice committed
            if (tid < 112) {                 // push own slice to 7 peers (16B each)
                float4 v4 = reinterpret_cast<const float4*>(&hbuf[nxt][rank * 64])[pslot];
                uint32_t laddr = base_u32 + (uint32_t)(nxt * 512 + rank * 64 + pslot * 4) * 4u;
                uint32_t ra;
                asm volatile("mapa.shared::cluster.u32 %0, %1, %2;" : "=r"(ra) : "r"(laddr), "r"(pr));
                asm volatile("st.shared::cluster.v4.f32 [%0], {%1,%2,%3,%4};"
                             :: "r"(ra), "f"(v4.x), "f"(v4.y), "f"(v4.z), "f"(v4.w) : "memory");
            }
            asm volatile("barrier.cluster.arrive.aligned;" ::: "memory");
            if (ks == 0 && t + 1 < LL) xnext = xp[(size_t)(t + 1) * HH + j];
            cur = nxt;
            asm volatile("barrier.cluster.wait.aligned;" ::: "memory");
        }
        // bulk z flush: 256 threads, two values each
#pragma unroll
        for (int q = 0; q < 2; q++) {
            int idx = tid + q * 256;
            int fs = idx >> 6, fc = idx & 63;
            zb[(size_t)(t0 + fs) * HH + rank * 64 + fc] = zstage[fs][fc];
        }
    }
}

// ---------------- row sums of fp16 P ----------------
__global__ void __launch_bounds__(256) rowsum_h_kernel(
    const __half* __restrict__ P, float* __restrict__ rs)
{
    int warp = threadIdx.x >> 5, lane = threadIdx.x & 31;
    int row = blockIdx.x * 8 + warp;
    const uint4* pr = reinterpret_cast<const uint4*>(P + (size_t)row * LL);
    float s = 0.f;
#pragma unroll
    for (int i = 0; i < 8; i++) {
        uint4 v = pr[i * 32 + lane];
        __half2 h0 = *reinterpret_cast<__half2*>(&v.x);
        __half2 h1 = *reinterpret_cast<__half2*>(&v.y);
        __half2 h2 = *reinterpret_cast<__half2*>(&v.z);
        __half2 h3 = *reinterpret_cast<__half2*>(&v.w);
        float2 f0 = __half22float2(h0), f1 = __half22float2(h1);
        float2 f2 = __half22float2(h2), f3 = __half22float2(h3);
        s += (f0.x + f0.y) + (f1.x + f1.y) + (f2.x + f2.y) + (f3.x + f3.y);
    }
#pragma unroll
    for (int m = 16; m; m >>= 1) s += __shfl_xor_sync(0xffffffffu, s, m);
    if (lane == 0) rs[row] = s;
}

// ---------------- row 0 fixup: mean of z -> catA hi/lo/hi ----------------
__global__ void __launch_bounds__(512) row0_kernel(
    const float* __restrict__ z, __half* __restrict__ catA)
{
    int b = blockIdx.x, h = threadIdx.x;
    const float* zb = z + (size_t)b * LL * HH + h;
    float s = 0.f;
#pragma unroll 8
    for (int m = 0; m < LL; m++) s += zb[(size_t)m * HH];
    float v = s * (1.0f / LL);
    __half hi = __float2half_rn(v);
    __half lo = __float2half_rn(v - __half2float(hi));
    size_t rb = (size_t)b * LL * 3072;
    catA[rb + h] = hi;
    catA[rb + 1024 + h] = lo;
    catA[rb + 2048 + h] = hi;
}

// ---------------- launch ----------------
extern "C" void kernel_launch(void* const* d_in, const int* in_sizes, int n_in,
                              void* d_out, int out_size)
{
    (void)in_sizes; (void)n_in; (void)out_size;
    const int*   batch = (const int*)  d_in[0];
    const float* emb   = (const float*)d_in[1];
    const float* W_ih  = (const float*)d_in[2];
    const float* b_ih  = (const float*)d_in[3];
    const float* W_hh  = (const float*)d_in[4];
    const float* b_hh  = (const float*)d_in[5];
    const float* W_c   = (const float*)d_in[6];
    const float* b_c   = (const float*)d_in[7];
    const float* W_d   = (const float*)d_in[8];
    const float* b_d   = (const float*)d_in[9];
    float* out = (float*)d_out;

    float *table, *xproj, *zbuf, *rs;
    __half *zh, *zTh, *Ph, *embA, *WihB, *catA, *Wc2, *decA, *Wd2;
    cudaGetSymbolAddress((void**)&table, g_table);
    cudaGetSymbolAddress((void**)&xproj, g_xproj);
    cudaGetSymbolAddress((void**)&zbuf,  g_z);
    cudaGetSymbolAddress((void**)&rs,    g_rowsum);
    cudaGetSymbolAddress((void**)&zh,    g_zh);
    cudaGetSymbolAddress((void**)&zTh,   g_zTh);
    cudaGetSymbolAddress((void**)&Ph,    g_Ph);
    cudaGetSymbolAddress((void**)&embA,  g_embA);
    cudaGetSymbolAddress((void**)&WihB,  g_WihB);
    cudaGetSymbolAddress((void**)&catA,  g_catA);
    cudaGetSymbolAddress((void**)&Wc2,   g_Wc2);
    cudaGetSymbolAddress((void**)&decA,  g_decA);
    cudaGetSymbolAddress((void**)&Wd2,   g_Wd2);

    cudaFuncSetAttribute(hmma_kernel<0>, cudaFuncAttributeMaxDynamicSharedMemorySize, HM_SMEM);
    cudaFuncSetAttribute(hmma_kernel<1>, cudaFuncAttributeMaxDynamicSharedMemorySize, HM_SMEM);
    cudaFuncSetAttribute(hmma_kernel<2>, cudaFuncAttributeMaxDynamicSharedMemorySize, HM_SMEM);
    cudaFuncSetAttribute(hmma_kernel<3>, cudaFuncAttributeMaxDynamicSharedMemorySize, HM_SMEM);

    // 1. table = emb @ W_ih^T + b_ih via HMMA 3-term split (K=1536)
    split3h_kernel<<<dim3(1, TPAD), 256>>>(emb, 512, embA, 1536, 0, 1024, 512, VV);
    split3h_kernel<<<dim3(1, HH),   256>>>(W_ih, 512, WihB, 1536, 0, 512, 1024, HH);
    hmma_kernel<0><<<dim3(HH / 128, TPAD / 128), 256, HM_SMEM>>>(
        embA, 1536, WihB, 1536, b_ih, table, 1536 / 32, HH, HH);

    // 2. xproj = table[batch]
    gather_kernel<<<(BB * LL * HH / 4) / 256, 256>>>(batch, table, xproj);

    // 3. RNN scan (8-CTA cluster per batch, 256 thr, conflict-free layout)
    {
        cudaLaunchConfig_t cfg = {};
        cfg.gridDim = dim3(64, 1, 1);
        cfg.blockDim = dim3(256, 1, 1);
        cfg.dynamicSmemBytes = 0;
        cfg.stream = 0;
        cudaLaunchAttribute attr[1];
        attr[0].id = cudaLaunchAttributeClusterDimension;
        attr[0].val.clusterDim.x = 8;
        attr[0].val.clusterDim.y = 1;
        attr[0].val.clusterDim.z = 1;
        cfg.attrs = attr;
        cfg.numAttrs = 1;
        cudaLaunchKernelEx(&cfg, rnn_kernel, (const float*)xproj, W_hh, b_hh, zbuf);
    }

    // 4. z -> fp16 (row-major + transposed + catA z-parts)
    zprep_kernel<<<dim3(LL / 32, HH / 32, BB), dim3(32, 32)>>>(zbuf, zh, zTh, catA);

    // 5. P = exp(mask(z zT)) fp16 via HMMA (triangular tiles)
    hmma_kernel<2><<<dim3(LL / 128, LL / 128, BB), 256, HM_SMEM>>>(
        zh, HH, zh, HH, nullptr, Ph, HH / 32, LL, LL);

    // 6. row sums
    rowsum_h_kernel<<<(BB * LL) / 8, 256>>>(Ph, rs);

    // 7. attv -> catA hi/lo/hi via HMMA (triangular K)
    hmma_kernel<3><<<dim3(HH / 128, LL / 128, BB), 256, HM_SMEM>>>(
        Ph, LL, zTh, LL, rs, catA, 0, HH, HH);

    // 8. row 0 fixup
    row0_kernel<<<BB, 512>>>(zbuf, catA);

    // 9. dec (fp16 hi/lo, fused) = [attv | z] @ W_c^T + b_c via 3-term split (K=3072)
    split3h_kernel<<<dim3(2, HH), 256>>>(W_c, 1024, Wc2, 3072, 0, 1024, 2048, HH);
    hmma_kernel<1><<<dim3(HH / 128, BB * LL / 128), 256, HM_SMEM>>>(
        catA, 3072, Wc2, 3072, b_c, decA, 3072 / 32, 1024, HH);

    // 10. logits = dec @ W_d^T + b_d via 2-term split (K=1024)
    split2h_kernel<<<dim3(1, NPAD), 256>>>(W_d, 512, Wd2, 1024, 0, 512, VV);
    hmma_kernel<0><<<dim3(NPAD / 128, BB * LL / 128), 256, HM_SMEM>>>(
        decA, 1024, Wd2, 1024, b_d, out, 1024 / 32, VV, VV);
}

// round 12
// speedup vs baseline: 1.8919x; 1.0435x over previous
#include <cuda_runtime.h>
#include <cuda_fp16.h>
#include <cstdint>
#include <cmath>

#define BB 8
#define LL 2048
#define VV 10000
#define EE 512
#define HH 512
#define NPAD 10112   // 79 * 128
#define TPAD 10112

// ---------------- device-global scratch ----------------
__device__ float g_table[TPAD * HH];          // emb @ W_ih^T + b_ih (padded rows)
__device__ float g_xproj[BB * LL * HH];
__device__ float g_z[BB * LL * HH];
__device__ float g_rowsum[BB * LL];

__device__ __half g_zh[(size_t)BB * LL * HH];        // z fp16 row-major (scores)
__device__ __half g_zTh[(size_t)BB * HH * LL];       // z fp16 transposed (attgemm B)
__device__ __half g_Ph[(size_t)BB * LL * LL];        // exp(scores) fp16; upper-tri stays 0 (BSS)

__device__ __half g_embA[(size_t)TPAD * 1536];       // [emb_hi|emb_lo|emb_hi]
__device__ __half g_WihB[(size_t)HH * 1536];         // [Wih_hi|Wih_hi|Wih_lo]
__device__ __half g_catA[(size_t)BB * LL * 3072];    // [attv_hi|z_hi|attv_lo|z_lo|attv_hi|z_hi]
__device__ __half g_Wc2[(size_t)HH * 3072];          // [Wc_hi|Wc_hi|Wc_lo]
__device__ __half g_decA[(size_t)BB * LL * 512];     // dec fp16 (1-term, W_c epilogue)
__device__ __half g_Wd2[(size_t)NPAD * 512];         // Wd fp16 (1-term)

// ====================== PTX helpers ======================
__device__ __forceinline__ uint32_t smem_u32(const void* p) {
    uint32_t a;
    asm("{ .reg .u64 t; cvta.to.shared.u64 t, %1; cvt.u32.u64 %0, t; }" : "=r"(a) : "l"(p));
    return a;
}
__device__ __forceinline__ void cpa16(uint32_t dst, const void* src) {
    asm volatile("cp.async.cg.shared.global [%0], [%1], 16;" :: "r"(dst), "l"(src) : "memory");
}
__device__ __forceinline__ void ldm_x4(uint32_t* r, uint32_t a) {
    asm volatile("ldmatrix.sync.aligned.m8n8.x4.shared.b16 {%0,%1,%2,%3}, [%4];"
        : "=r"(r[0]), "=r"(r[1]), "=r"(r[2]), "=r"(r[3]) : "r"(a));
}
__device__ __forceinline__ void mma16816(float* d, const uint32_t* a, const uint32_t* b) {
    asm volatile("mma.sync.aligned.m16n8k16.row.col.f32.f16.f16.f32 "
        "{%0,%1,%2,%3}, {%4,%5,%6,%7}, {%8,%9}, {%0,%1,%2,%3};"
        : "+f"(d[0]), "+f"(d[1]), "+f"(d[2]), "+f"(d[3])
        : "r"(a[0]), "r"(a[1]), "r"(a[2]), "r"(a[3]), "r"(b[0]), "r"(b[1]));
}
// packed fp32x2 FMA (Blackwell base ISA)
__device__ __forceinline__ void fma2(unsigned long long& d,
                                     unsigned long long a, unsigned long long b) {
    asm("fma.rn.f32x2 %0, %1, %2, %0;" : "+l"(d) : "l"(a), "l"(b));
}
__device__ __forceinline__ float2 upk2(unsigned long long v) {
    float x, y;
    asm("mov.b64 {%0,%1}, %2;" : "=f"(x), "=f"(y) : "l"(v));
    return make_float2(x, y);
}

// ====================== shared HMMA mainloop ======================
// C_tile[128,128] += A[128 rows, K] * B[128 rows, K]^T ; BK=32, 3-stage cp.async
#define HM_STAGE 20480
#define HM_SMEM (3 * HM_STAGE)

__device__ __forceinline__ void hmma_mainloop(
    const __half* __restrict__ Ab, int lda,
    const __half* __restrict__ Bb, int ldb, int NC,
    uint32_t smb, int tid, int lane, int wm, int wn, float acc[2][8][4])
{
    auto load_stage = [&](int c) {
        const uint32_t sa = smb + (c % 3) * HM_STAGE;
        const uint32_t sbp = sa + 10240;
        const __half* Ag = Ab + c * 32;
        const __half* Bg = Bb + c * 32;
#pragma unroll
        for (int i = 0; i < 2; i++) {
            int ch = tid + i * 256;
            int r = ch >> 2, seg = ch & 3;
            cpa16(sa + r * 80 + seg * 16, Ag + (size_t)r * lda + seg * 8);
        }
#pragma unroll
        for (int i = 0; i < 2; i++) {
            int ch = tid + i * 256;
            int r = ch >> 2, seg = ch & 3;
            cpa16(sbp + r * 80 + seg * 16, Bg + (size_t)r * ldb + seg * 8);
        }
        asm volatile("cp.async.commit_group;" ::: "memory");
    };

    load_stage(0);
    load_stage(1);

    for (int i = 0; i < NC; i++) {
        if (i + 1 < NC) asm volatile("cp.async.wait_group 1;" ::: "memory");
        else            asm volatile("cp.async.wait_group 0;" ::: "memory");
        __syncthreads();
        if (i + 2 < NC) load_stage(i + 2);

        const uint32_t sa = smb + (i % 3) * HM_STAGE;
        const uint32_t sbp = sa + 10240;
#pragma unroll
        for (int ks = 0; ks < 2; ks++) {
            uint32_t areg[2][4];
            uint32_t breg[8][2];
#pragma unroll
            for (int mi = 0; mi < 2; mi++) {
                int row = wm + mi * 16 + (lane & 15);
                ldm_x4(areg[mi], sa + row * 80 + ks * 32 + ((lane >> 4) << 4));
            }
#pragma unroll
            for (int nq = 0; nq < 4; nq++) {
                int n = wn + nq * 16 + (lane & 7) + ((lane >> 4) << 3);
                uint32_t t[4];
                ldm_x4(t, sbp + n * 80 + ks * 32 + (((lane >> 3) & 1) << 4));
                breg[nq * 2][0] = t[0]; breg[nq * 2][1] = t[1];
                breg[nq * 2 + 1][0] = t[2]; breg[nq * 2 + 1][1] = t[3];
            }
#pragma unroll
            for (int mi = 0; mi < 2; mi++)
#pragma unroll
                for (int ni = 0; ni < 8; ni++)
                    mma16816(acc[mi][ni], areg[mi], breg[ni]);
        }
    }
}

// MODE 0: bias -> fp32 C (W_d logits, table)
// MODE 1: bias -> dec fp16 1-term (W_c)
// MODE 2: scores: z_h @ z_h^T, exp+mask -> P fp16 (triangular tiles)
// MODE 3: attgemm: P_h @ zT_h^T, scale by 1/rowsum -> catA hi/lo/hi fp16
template<int MODE>
__global__ void __launch_bounds__(256, 2) hmma_kernel(
    const __half* __restrict__ Abase, int lda,
    const __half* __restrict__ Bbase, int ldb,
    const float* __restrict__ aux, void* __restrict__ Cptr,
    int NCin, int Nout, int Nvalid)
{
    extern __shared__ char smem[];
    const uint32_t smb = smem_u32(smem);
    const int tid = threadIdx.x;
    const int wid = tid >> 5, lane = tid & 31;
    const int wm = (wid & 3) * 32, wn = (wid >> 2) * 64;
    const int bm = blockIdx.y * 128, bn = blockIdx.x * 128;
    const int bz = blockIdx.z;

    if (MODE == 2 && blockIdx.x > blockIdx.y) return;

    const __half* Ab;
    const __half* Bb;
    int NC = NCin;
    if (MODE == 2) {
        Ab = Abase + (size_t)bz * LL * HH + (size_t)bm * lda;
        Bb = Abase + (size_t)bz * LL * HH + (size_t)bn * ldb;
    } else if (MODE == 3) {
        Ab = Abase + (size_t)bz * LL * LL + (size_t)bm * lda;
        Bb = Bbase + (size_t)bz * HH * LL + (size_t)bn * ldb;
        NC = (blockIdx.y + 1) * 4;
    } else {
        Ab = Abase + (size_t)bm * lda;
        Bb = Bbase + (size_t)bn * ldb;
    }

    float acc[2][8][4];
#pragma unroll
    for (int mi = 0; mi < 2; mi++)
#pragma unroll
        for (int ni = 0; ni < 8; ni++)
#pragma unroll
            for (int j = 0; j < 4; j++) acc[mi][ni][j] = 0.f;

    hmma_mainloop(Ab, lda, Bb, ldb, NC, smb, tid, lane, wm, wn, acc);

    const int r0 = lane >> 2, c0 = (lane & 3) * 2;

    if (MODE == 0) {
        float* C = (float*)Cptr;
#pragma unroll
        for (int mi = 0; mi < 2; mi++) {
#pragma unroll
            for (int ni = 0; ni < 8; ni++) {
                int gn = bn + wn + ni * 8 + c0;
                if (gn >= Nvalid) continue;
                float b0 = aux[gn], b1 = aux[gn + 1];
                int gm = bm + wm + mi * 16 + r0;
                *reinterpret_cast<float2*>(C + (size_t)gm * Nout + gn) =
                    make_float2(acc[mi][ni][0] + b0, acc[mi][ni][1] + b1);
                *reinterpret_cast<float2*>(C + (size_t)(gm + 8) * Nout + gn) =
                    make_float2(acc[mi][ni][2] + b0, acc[mi][ni][3] + b1);
            }
        }
    } else if (MODE == 1) {
        __half* D = (__half*)Cptr;   // dec fp16 [M, 512]
#pragma unroll
        for (int mi = 0; mi < 2; mi++) {
#pragma unroll
            for (int ni = 0; ni < 8; ni++) {
                int gn = bn + wn + ni * 8 + c0;
                float b0 = aux[gn], b1 = aux[gn + 1];
#pragma unroll
                for (int half_ : {0, 1}) {
                    int gm = bm + wm + mi * 16 + r0 + half_ * 8;
                    __half2 hi;
                    hi.x = __float2half_rn(acc[mi][ni][half_ * 2 + 0] + b0);
                    hi.y = __float2half_rn(acc[mi][ni][half_ * 2 + 1] + b1);
                    *reinterpret_cast<__half2*>(D + (size_t)gm * Nout + gn) = hi;
                }
            }
        }
    } else if (MODE == 2) {
        __half* P = (__half*)Cptr + (size_t)bz * LL * LL;
#pragma unroll
        for (int mi = 0; mi < 2; mi++) {
#pragma unroll
            for (int ni = 0; ni < 8; ni++) {
                int gmc = bn + wn + ni * 8 + c0;       // column m
#pragma unroll
                for (int half_ : {0, 1}) {
                    int gl = bm + wm + mi * 16 + r0 + half_ * 8;
                    float v0 = acc[mi][ni][half_ * 2 + 0];
                    float v1 = acc[mi][ni][half_ * 2 + 1];
                    __half2 e;
                    e.x = __float2half_rn((gmc     < gl) ? __expf(v0) : 0.f);
                    e.y = __float2half_rn((gmc + 1 < gl) ? __expf(v1) : 0.f);
                    *reinterpret_cast<__half2*>(P + (size_t)gl * LL + gmc) = e;
                }
            }
        }
    } else {  // MODE 3: write attv hi/lo/hi directly into catA [row, 3072]
        __half* D = (__half*)Cptr;
        const float* rsb = aux + (size_t)bz * LL;
#pragma unroll
        for (int mi = 0; mi < 2; mi++) {
#pragma unroll
            for (int ni = 0; ni < 8; ni++) {
                int gn = bn + wn + ni * 8 + c0;
#pragma unroll
                for (int half_ : {0, 1}) {
                    int gm = bm + wm + mi * 16 + r0 + half_ * 8;
                    float inv = 1.f / rsb[gm];   // row 0 -> NaN, overwritten by row0_kernel
                    float v0 = acc[mi][ni][half_ * 2 + 0] * inv;
                    float v1 = acc[mi][ni][half_ * 2 + 1] * inv;
                    __half2 hi, lo;
                    hi.x = __float2half_rn(v0);
                    hi.y = __float2half_rn(v1);
                    lo.x = __float2half_rn(v0 - __half2float(hi.x));
                    lo.y = __float2half_rn(v1 - __half2float(hi.y));
                    size_t rb = ((size_t)bz * LL + gm) * 3072;
                    *reinterpret_cast<__half2*>(D + rb + gn) = hi;
                    *reinterpret_cast<__half2*>(D + rb + 1024 + gn) = lo;
                    *reinterpret_cast<__half2*>(D + rb + 2048 + gn) = hi;
                }
            }
        }
    }
}

// ---------------- z prep: zh fp16 + zT fp16 + catA z hi/lo parts ----------------
__global__ void __launch_bounds__(1024) zprep_kernel(
    const float* __restrict__ z, __half* __restrict__ zh, __half* __restrict__ zT,
    __half* __restrict__ catA)
{
    __shared__ __half tile[32][33];
    const int b = blockIdx.z;
    const int t0 = blockIdx.x * 32, j0 = blockIdx.y * 32;
    const int tx = threadIdx.x, ty = threadIdx.y;
    const float* zb = z + (size_t)b * LL * HH;
    float zv = zb[(size_t)(t0 + ty) * HH + j0 + tx];
    __half h = __float2half_rn(zv);
    __half lo = __float2half_rn(zv - __half2float(h));
    zh[(size_t)b * LL * HH + (size_t)(t0 + ty) * HH + j0 + tx] = h;
    size_t rb = ((size_t)b * LL + t0 + ty) * 3072 + j0 + tx;
    catA[rb + 512]  = h;
    catA[rb + 1536] = lo;
    catA[rb + 2560] = h;
    tile[ty][tx] = h;
    __syncthreads();
    zT[(size_t)b * HH * LL + (size_t)(j0 + ty) * LL + t0 + tx] = tile[tx][ty];
}

// ---------------- split fp32 -> fp16 hi/lo (K-concat) ----------------
__global__ void __launch_bounds__(256) split3h_kernel(
    const float* __restrict__ src, int Ksrc,
    __half* __restrict__ dst, int Kdst,
    int off_hi1, int off_hi2, int off_lo, int Mvalid)
{
    int row = blockIdx.y;
    int col = (blockIdx.x * 256 + threadIdx.x) * 2;
    if (col >= Ksrc) return;
    float2 v = make_float2(0.f, 0.f);
    if (row < Mvalid) v = *reinterpret_cast<const float2*>(src + (size_t)row * Ksrc + col);
    __half2 hi, lo;
    hi.x = __float2half_rn(v.x);
    hi.y = __float2half_rn(v.y);
    lo.x = __float2half_rn(v.x - __half2float(hi.x));
    lo.y = __float2half_rn(v.y - __half2float(hi.y));
    size_t rb = (size_t)row * Kdst;
    *reinterpret_cast<__half2*>(dst + rb + off_hi1 + col) = hi;
    *reinterpret_cast<__half2*>(dst + rb + off_hi2 + col) = hi;
    *reinterpret_cast<__half2*>(dst + rb + off_lo + col) = lo;
}

// 1-term: fp16 hi only, K=512
__global__ void __launch_bounds__(256) split1h_kernel(
    const float* __restrict__ src, __half* __restrict__ dst, int Mvalid)
{
    int row = blockIdx.y;
    int col = threadIdx.x * 2;
    float2 v = make_float2(0.f, 0.f);
    if (row < Mvalid) v = *reinterpret_cast<const float2*>(src + (size_t)row * 512 + col);
    __half2 hi;
    hi.x = __float2half_rn(v.x);
    hi.y = __float2half_rn(v.y);
    *reinterpret_cast<__half2*>(dst + (size_t)row * 512 + col) = hi;
}

// ---------------- token gather ----------------
__global__ void __launch_bounds__(256) gather_kernel(
    const int* __restrict__ batch, const float* __restrict__ table, float* __restrict__ xproj)
{
    int g = blockIdx.x * 256 + threadIdx.x;
    int row = g >> 7;
    int c = g & 127;
    int tok = batch[row];
    reinterpret_cast<float4*>(xproj)[g] =
        reinterpret_cast<const float4*>(table + (size_t)tok * HH)[c];
}

// ---------------- RNN scan v4: mbarrier handshake instead of cluster barrier ----------------
// Per step: compute -> writers store local h + zstage -> __syncthreads ->
// 112 pushers st.shared::cluster.v4 + remote mbarrier.arrive.release.cluster ->
// all threads try_wait.acquire.cluster on own mbar[nxt] (count=112 = 7 peers x 16 pushers).
// Lockstep safety: a CTA sends step-t data only after its quad finished reading
// buf[(t-1)%2]; a peer receives all step-t data before it may write buf[(t+1)%2]
// (same parity as (t-1)%2), so two buffers + two mbars suffice.
__global__ void __launch_bounds__(256, 1) rnn_kernel(
    const float* __restrict__ xproj, const float* __restrict__ Whh,
    const float* __restrict__ bhh, float* __restrict__ z)
{
    __shared__ __align__(16) float hbuf[2][512];
    __shared__ float zstage[8][64];
    __shared__ __align__(8) unsigned long long mbar[2];
    unsigned rank;
    asm("mov.u32 %0, %%cluster_ctarank;" : "=r"(rank));
    const int batch = blockIdx.x >> 3;
    const int tid = threadIdx.x;
    const int jl = tid >> 2;        // output 0..63
    const int ks = tid & 3;         // k-slice 0..3
    const int j = (int)rank * 64 + jl;

    // W row j, k-interleaved: slot i holds global float4 index 4*i+ks
    unsigned long long w2[64];
    {
        const ulonglong2* wr = reinterpret_cast<const ulonglong2*>(Whh + (size_t)j * HH);
#pragma unroll
        for (int i = 0; i < 32; i++) {
            ulonglong2 q = wr[i * 4 + ks];
            w2[2 * i] = q.x; w2[2 * i + 1] = q.y;
        }
    }
    const float bj = bhh[j];

    for (int i = tid; i < 2 * 512; i += 256) (&hbuf[0][0])[i] = 0.f;

    const uint32_t hbase = smem_u32(&hbuf[0][0]);
    uint32_t mb0 = smem_u32(&mbar[0]);
    uint32_t mb1 = smem_u32(&mbar[1]);
    if (tid == 0) {
        asm volatile("mbarrier.init.shared.b64 [%0], %1;" :: "r"(mb0), "r"(112u) : "memory");
        asm volatile("mbarrier.init.shared.b64 [%0], %1;" :: "r"(mb1), "r"(112u) : "memory");
    }
    __syncthreads();
    // all cluster SMEM zeroed and mbars initialized before any remote traffic
    asm volatile("barrier.cluster.arrive.aligned;\n\tbarrier.cluster.wait.aligned;" ::: "memory");

    const float* xp = xproj + (size_t)batch * LL * HH;
    float* zb = z + (size_t)batch * LL * HH;

    // pusher mapping: tid<112 -> peer pr (skip own rank), float4 slot pslot
    const int pr_raw = tid >> 4;
    const int pr = (pr_raw >= (int)rank) ? pr_raw + 1 : pr_raw;
    const int pslot = tid & 15;
    uint32_t rdst0 = 0, rdst1 = 0, rmb0 = 0, rmb1 = 0;
    if (tid < 112) {
        uint32_t la0 = hbase + (uint32_t)(0 * 512 + rank * 64 + pslot * 4) * 4u;
        uint32_t la1 = hbase + (uint32_t)(1 * 512 + rank * 64 + pslot * 4) * 4u;
        asm volatile("mapa.shared::cluster.u32 %0, %1, %2;" : "=r"(rdst0) : "r"(la0), "r"(pr));
        asm volatile("mapa.shared::cluster.u32 %0, %1, %2;" : "=r"(rdst1) : "r"(la1), "r"(pr));
        asm volatile("mapa.shared::cluster.u32 %0, %1, %2;" : "=r"(rmb0) : "r"(mb0), "r"(pr));
        asm volatile("mapa.shared::cluster.u32 %0, %1, %2;" : "=r"(rmb1) : "r"(mb1), "r"(pr));
    }

    int cur = 0;
    unsigned par0 = 0, par1 = 0;
    float xnext = (ks == 0) ? xp[j] : 0.f;
    for (int t0 = 0; t0 < LL; t0 += 8) {
#pragma unroll 1
        for (int tt = 0; tt < 8; tt++) {
            const int t = t0 + tt;
            const float xcur = xnext;

            const ulonglong2* hp = reinterpret_cast<const ulonglong2*>(&hbuf[cur][0]);
            unsigned long long acc0 = 0ull, acc1 = 0ull, acc2 = 0ull, acc3 = 0ull;
#pragma unroll
            for (int i = 0; i < 16; i++) {
                ulonglong2 hv0 = hp[(2 * i) * 4 + ks];
                ulonglong2 hv1 = hp[(2 * i + 1) * 4 + ks];
                fma2(acc0, w2[4 * i + 0], hv0.x);
                fma2(acc1, w2[4 * i + 1], hv0.y);
                fma2(acc2, w2[4 * i + 2], hv1.x);
                fma2(acc3, w2[4 * i + 3], hv1.y);
            }
            float2 f0 = upk2(acc0), f1 = upk2(acc1);
            float2 f2 = upk2(acc2), f3 = upk2(acc3);
            float s = ((f0.x + f0.y) + (f1.x + f1.y)) + ((f2.x + f2.y) + (f3.x + f3.y));
            s += __shfl_xor_sync(0xffffffffu, s, 1);
            s += __shfl_xor_sync(0xffffffffu, s, 2);

            const int nxt = cur ^ 1;
            if (ks == 0) {
                float hv = tanhf(s + xcur + bj);
                zstage[tt][jl] = hv;
                hbuf[nxt][j] = hv;          // own slice, local copy
            }
            __syncthreads();                 // local slice committed for pushers/consumers
            if (tid < 112) {
                float4 v4 = reinterpret_cast<const float4*>(&hbuf[nxt][rank * 64])[pslot];
                uint32_t rd = nxt ? rdst1 : rdst0;
                uint32_t rm = nxt ? rmb1 : rmb0;
                asm volatile("st.shared::cluster.v4.f32 [%0], {%1,%2,%3,%4};"
                             :: "r"(rd), "f"(v4.x), "f"(v4.y), "f"(v4.z), "f"(v4.w) : "memory");
                asm volatile("mbarrier.arrive.release.cluster.shared::cluster.b64 _, [%0];"
                             :: "r"(rm) : "memory");
            }
            if (ks == 0 && t + 1 < LL) xnext = xp[(size_t)(t + 1) * HH + j];

            // wait for all 7 peers' slices (own slice ordered by __syncthreads above)
            {
                uint32_t mb = nxt ? mb1 : mb0;
                unsigned par = nxt ? par1 : par0;
                asm volatile(
                    "{\n\t.reg .pred P;\n\t"
                    "WL%=:\n\t"
                    "mbarrier.try_wait.parity.acquire.cluster.shared::cta.b64 P, [%0], %1, 0x989680;\n\t"
                    "@!P bra WL%=;\n\t}"
                    :: "r"(mb), "r"(par) : "memory");
                if (nxt) par1 ^= 1; else par0 ^= 1;
            }
            cur = nxt;
        }
        // bulk z flush: 256 threads, two values each (zstage ordered by per-step syncthreads)
#pragma unroll
        for (int q = 0; q < 2; q++) {
            int idx = tid + q * 256;
            int fs = idx >> 6, fc = idx & 63;
            zb[(size_t)(t0 + fs) * HH + rank * 64 + fc] = zstage[fs][fc];
        }
        __syncthreads();   // flush reads done before zstage reuse
    }
}

// ---------------- row sums of fp16 P ----------------
__global__ void __launch_bounds__(256) rowsum_h_kernel(
    const __half* __restrict__ P, float* __restrict__ rs)
{
    int warp = threadIdx.x >> 5, lane = threadIdx.x & 31;
    int row = blockIdx.x * 8 + warp;
    const uint4* pr = reinterpret_cast<const uint4*>(P + (size_t)row * LL);
    float s = 0.f;
#pragma unroll
    for (int i = 0; i < 8; i++) {
        uint4 v = pr[i * 32 + lane];
        __half2 h0 = *reinterpret_cast<__half2*>(&v.x);
        __half2 h1 = *reinterpret_cast<__half2*>(&v.y);
        __half2 h2 = *reinterpret_cast<__half2*>(&v.z);
        __half2 h3 = *reinterpret_cast<__half2*>(&v.w);
        float2 f0 = __half22float2(h0), f1 = __half22float2(h1);
        float2 f2 = __half22float2(h2), f3 = __half22float2(h3);
        s += (f0.x + f0.y) + (f1.x + f1.y) + (f2.x + f2.y) + (f3.x + f3.y);
    }
#pragma unroll
    for (int m = 16; m; m >>= 1) s += __shfl_xor_sync(0xffffffffu, s, m);
    if (lane == 0) rs[row] = s;
}

// ---------------- row 0 fixup: mean of z -> catA hi/lo/hi ----------------
__global__ void __launch_bounds__(512) row0_kernel(
    const float* __restrict__ z, __half* __restrict__ catA)
{
    int b = blockIdx.x, h = threadIdx.x;
    const float* zb = z + (size_t)b * LL * HH + h;
    float s = 0.f;
#pragma unroll 8
    for (int m = 0; m < LL; m++) s += zb[(size_t)m * HH];
    float v = s * (1.0f / LL);
    __half hi = __float2half_rn(v);
    __half lo = __float2half_rn(v - __half2float(hi));
    size_t rb = (size_t)b * LL * 3072;
    catA[rb + h] = hi;
    catA[rb + 1024 + h] = lo;
    catA[rb + 2048 + h] = hi;
}

// ---------------- launch ----------------
extern "C" void kernel_launch(void* const* d_in, const int* in_sizes, int n_in,
                              void* d_out, int out_size)
{
    (void)in_sizes; (void)n_in; (void)out_size;
    const int*   batch = (const int*)  d_in[0];
    const float* emb   = (const float*)d_in[1];
    const float* W_ih  = (const float*)d_in[2];
    const float* b_ih  = (const float*)d_in[3];
    const float* W_hh  = (const float*)d_in[4];
    const float* b_hh  = (const float*)d_in[5];
    const float* W_c   = (const float*)d_in[6];
    const float* b_c   = (const float*)d_in[7];
    const float* W_d   = (const float*)d_in[8];
    const float* b_d   = (const float*)d_in[9];
    float* out = (float*)d_out;

    float *table, *xproj, *zbuf, *rs;
    __half *zh, *zTh, *Ph, *embA, *WihB, *catA, *Wc2, *decA, *Wd2;
    cudaGetSymbolAddress((void**)&table, g_table);
    cudaGetSymbolAddress((void**)&xproj, g_xproj);
    cudaGetSymbolAddress((void**)&zbuf,  g_z);
    cudaGetSymbolAddress((void**)&rs,    g_rowsum);
    cudaGetSymbolAddress((void**)&zh,    g_zh);
    cudaGetSymbolAddress((void**)&zTh,   g_zTh);
    cudaGetSymbolAddress((void**)&Ph,    g_Ph);
    cudaGetSymbolAddress((void**)&embA,  g_embA);
    cudaGetSymbolAddress((void**)&WihB,  g_WihB);
    cudaGetSymbolAddress((void**)&catA,  g_catA);
    cudaGetSymbolAddress((void**)&Wc2,   g_Wc2);
    cudaGetSymbolAddress((void**)&decA,  g_decA);
    cudaGetSymbolAddress((void**)&Wd2,   g_Wd2);

    cudaFuncSetAttribute(hmma_kernel<0>, cudaFuncAttributeMaxDynamicSharedMemorySize, HM_SMEM);
    cudaFuncSetAttribute(hmma_kernel<1>, cudaFuncAttributeMaxDynamicSharedMemorySize, HM_SMEM);
    cudaFuncSetAttribute(hmma_kernel<2>, cudaFuncAttributeMaxDynamicSharedMemorySize, HM_SMEM);
    cudaFuncSetAttribute(hmma_kernel<3>, cudaFuncAttributeMaxDynamicSharedMemorySize, HM_SMEM);

    // 1. table = emb @ W_ih^T + b_ih via HMMA 3-term split (K=1536)
    split3h_kernel<<<dim3(1, TPAD), 256>>>(emb, 512, embA, 1536, 0, 1024, 512, VV);
    split3h_kernel<<<dim3(1, HH),   256>>>(W_ih, 512, WihB, 1536, 0, 512, 1024, HH);
    hmma_kernel<0><<<dim3(HH / 128, TPAD / 128), 256, HM_SMEM>>>(
        embA, 1536, WihB, 1536, b_ih, table, 1536 / 32, HH, HH);

    // 2. xproj = table[batch]
    gather_kernel<<<(BB * LL * HH / 4) / 256, 256>>>(batch, table, xproj);

    // 3. RNN scan (8-CTA cluster per batch, mbarrier handshake)
    {
        cudaLaunchConfig_t cfg = {};
        cfg.gridDim = dim3(64, 1, 1);
        cfg.blockDim = dim3(256, 1, 1);
        cfg.dynamicSmemBytes = 0;
        cfg.stream = 0;
        cudaLaunchAttribute attr[1];
        attr[0].id = cudaLaunchAttributeClusterDimension;
        attr[0].val.clusterDim.x = 8;
        attr[0].val.clusterDim.y = 1;
        attr[0].val.clusterDim.z = 1;
        cfg.attrs = attr;
        cfg.numAttrs = 1;
        cudaLaunchKernelEx(&cfg, rnn_kernel, (const float*)xproj, W_hh, b_hh, zbuf);
    }

    // 4. z -> fp16 (row-major + transposed + catA z-parts)
    zprep_kernel<<<dim3(LL / 32, HH / 32, BB), dim3(32, 32)>>>(zbuf, zh, zTh, catA);

    // 5. P = exp(mask(z zT)) fp16 via HMMA (triangular tiles)
    hmma_kernel<2><<<dim3(LL / 128, LL / 128, BB), 256, HM_SMEM>>>(
        zh, HH, zh, HH, nullptr, Ph, HH / 32, LL, LL);

    // 6. row sums
    rowsum_h_kernel<<<(BB * LL) / 8, 256>>>(Ph, rs);

    // 7. attv -> catA hi/lo/hi via HMMA (triangular K)
    hmma_kernel<3><<<dim3(HH / 128, LL / 128, BB), 256, HM_SMEM>>>(
        Ph, LL, zTh, LL, rs, catA, 0, HH, HH);

    // 8. row 0 fixup
    row0_kernel<<<BB, 512>>>(zbuf, catA);

    // 9. dec (fp16, fused) = [attv | z] @ W_c^T + b_c via 3-term split (K=3072)
    split3h_kernel<<<dim3(2, HH), 256>>>(W_c, 1024, Wc2, 3072, 0, 1024, 2048, HH);
    hmma_kernel<1><<<dim3(HH / 128, BB * LL / 128), 256, HM_SMEM>>>(
        catA, 3072, Wc2, 3072, b_c, decA, 3072 / 32, 512, HH);

    // 10. logits = dec @ W_d^T + b_d via 1-term fp16 (K=512)
    split1h_kernel<<<dim3(1, NPAD), 256>>>(W_d, Wd2, VV);
    hmma_kernel<0><<<dim3(NPAD / 128, BB * LL / 128), 256, HM_SMEM>>>(
        decA, 512, Wd2, 512, b_d, out, 512 / 32, VV, VV);
}